// round 2
// baseline (speedup 1.0000x reference)
#include <cuda_runtime.h>
#include <cstddef>

// ---------------------------------------------------------------------------
// Pipeline:
//   stage1: x[1280,3,224,224] -> conv1(3->3,k3,s2) -> maxpool3 -> relu
//           -> g_pool1[1280,3,37,37]
//   stage2: conv2(3->1,k3,s2) -> maxpool3 -> relu -> 36->6 linear
//           -> g_nf[1280,6]
//   stage3: message passing + concat + fc1/fc2/fc3 -> out[64,6]
// ---------------------------------------------------------------------------

#define IMGS 1280

__device__ float g_pool1[IMGS * 3 * 37 * 37];   // 21 MB scratch
__device__ float g_nf[IMGS * 6];

// ---------------------------------------------------------------------------
// Stage 1: fused conv1 + maxpool3 + relu.
// Grid: (1280, 19). Each block handles up to G=2 pooled rows of one image.
// Pooled row p needs conv rows 3p..3p+2 -> input rows 6p..6p+6.
// Block loads 3ch x 13 rows x 224 cols = 35 KB smem.
// Each thread owns one pooled cell (p_local, q) and computes all 3 out
// channels from the shared 7x7x3 input window (maxpool is non-overlapping,
// so there is zero redundant conv work).
// ---------------------------------------------------------------------------
__global__ __launch_bounds__(128) void stage1_kernel(
    const float* __restrict__ nodes,
    const float* __restrict__ w1g,     // [3][3][3][3]
    const float* __restrict__ b1g)     // [3]
{
    const int img    = blockIdx.x;
    const int grp    = blockIdx.y;
    const int p_base = grp * 2;
    const int nrows  = (37 - p_base) < 2 ? (37 - p_base) : 2;   // 2 or 1
    const int cnt    = 6 * nrows + 1;                            // 13 or 7
    const int r0     = 6 * p_base;

    __shared__ float sIn[3 * 13 * 224];   // 34944 B
    const int tid = threadIdx.x;

    // ---- coalesced float4 load: global -> smem ----
    const int per_ch4 = cnt * 56;          // float4s per channel
    const int total4  = 3 * per_ch4;
    const float* src = nodes + (size_t)img * 150528;
    for (int i4 = tid; i4 < total4; i4 += blockDim.x) {
        int ci = i4 / per_ch4;
        int r  = i4 - ci * per_ch4;
        int rr = r / 56;
        int c4 = r - rr * 56;
        float4 v = *((const float4*)(src + ci * 50176 + (r0 + rr) * 224) + c4);
        ((float4*)sIn)[ci * 728 + rr * 56 + c4] = v;
    }

    // conv1 weights in registers (broadcast LDG, L1-served)
    float w[81];
#pragma unroll
    for (int i = 0; i < 81; i++) w[i] = w1g[i];
    const float bb0 = b1g[0], bb1 = b1g[1], bb2 = b1g[2];

    __syncthreads();

    const int cells = nrows * 37;
    if (tid < cells) {
        const int pl = tid / 37;
        const int q  = tid - pl * 37;

        float pool0 = -1e30f, pool1 = -1e30f, pool2 = -1e30f;
#pragma unroll
        for (int pr = 0; pr < 3; pr++) {
#pragma unroll
            for (int pc = 0; pc < 3; pc++) {
                float c0 = 0.f, c1 = 0.f, c2 = 0.f;
#pragma unroll
                for (int ci = 0; ci < 3; ci++) {
#pragma unroll
                    for (int kh = 0; kh < 3; kh++) {
                        const float* row =
                            &sIn[ci * 2912 + (6 * pl + 2 * pr + kh) * 224 +
                                 6 * q + 2 * pc];
#pragma unroll
                        for (int kw = 0; kw < 3; kw++) {
                            float v = row[kw];
                            c0 = fmaf(v, w[(0 * 3 + ci) * 9 + kh * 3 + kw], c0);
                            c1 = fmaf(v, w[(1 * 3 + ci) * 9 + kh * 3 + kw], c1);
                            c2 = fmaf(v, w[(2 * 3 + ci) * 9 + kh * 3 + kw], c2);
                        }
                    }
                }
                pool0 = fmaxf(pool0, c0 + bb0);
                pool1 = fmaxf(pool1, c1 + bb1);
                pool2 = fmaxf(pool2, c2 + bb2);
            }
        }
        const int p = p_base + pl;
        const size_t base = (size_t)img * 4107 + (size_t)p * 37 + q;
        g_pool1[base + 0 * 1369] = fmaxf(pool0, 0.f);
        g_pool1[base + 1 * 1369] = fmaxf(pool1, 0.f);
        g_pool1[base + 2 * 1369] = fmaxf(pool2, 0.f);
    }
}

// ---------------------------------------------------------------------------
// Stage 2: fused conv2 + maxpool3 + relu + 36->6 linear. One block per image.
// ---------------------------------------------------------------------------
__global__ __launch_bounds__(128) void stage2_kernel(
    const float* __restrict__ w2g,   // [1][3][3][3]
    const float* __restrict__ b2g,   // [1]
    const float* __restrict__ linw,  // [6][36]
    const float* __restrict__ linb)  // [6]
{
    const int img = blockIdx.x;
    const int tid = threadIdx.x;

    __shared__ float s[3 * 1369];   // 3 x 37 x 37
    __shared__ float s2[36];

    const float* src = g_pool1 + (size_t)img * 4107;
    for (int i = tid; i < 4107; i += blockDim.x) s[i] = src[i];

    float w[27];
#pragma unroll
    for (int i = 0; i < 27; i++) w[i] = w2g[i];
    const float bias = b2g[0];

    __syncthreads();

    if (tid < 36) {
        const int pr = tid / 6, pc = tid - 6 * (tid / 6);
        float pool = -1e30f;
#pragma unroll
        for (int r = 0; r < 3; r++) {
#pragma unroll
            for (int c = 0; c < 3; c++) {
                const int R = 3 * pr + r;    // conv2 row 0..17
                const int C = 3 * pc + c;
                float acc = bias;
#pragma unroll
                for (int ci = 0; ci < 3; ci++)
#pragma unroll
                    for (int kh = 0; kh < 3; kh++)
#pragma unroll
                        for (int kw = 0; kw < 3; kw++)
                            acc = fmaf(s[ci * 1369 + (2 * R + kh) * 37 +
                                         2 * C + kw],
                                       w[ci * 9 + kh * 3 + kw], acc);
                pool = fmaxf(pool, acc);
            }
        }
        s2[tid] = fmaxf(pool, 0.f);
    }
    __syncthreads();

    if (tid < 6) {
        float acc = linb[tid];
#pragma unroll
        for (int k = 0; k < 36; k++) acc = fmaf(s2[k], linw[tid * 36 + k], acc);
        g_nf[img * 6 + tid] = acc;
    }
}

// ---------------------------------------------------------------------------
// Stage 3: message passing + MLP head. One block per node (64 blocks).
// ---------------------------------------------------------------------------
__global__ __launch_bounds__(128) void stage3_kernel(
    const float* __restrict__ pos,     // [64,5,4,6]
    const float* __restrict__ attmap,  // [64,5,4,4]
    const float* __restrict__ framew, const float* __restrict__ frameb,
    const float* __restrict__ lastw,  const float* __restrict__ lastb,
    const float* __restrict__ fc1w,   const float* __restrict__ fc1b,
    const float* __restrict__ fc2w,   const float* __restrict__ fc2b,
    const float* __restrict__ fc3w,   const float* __restrict__ fc3b,
    float* __restrict__ out)
{
    const int n   = blockIdx.x;
    const int tid = threadIdx.x;

    __shared__ float msg[120];    // [f][j][d]
    __shared__ float feat[240];   // [f][n][12] : [0:6]=nodes_feature, [6:12]=pos_updata
    __shared__ float h1[120];
    __shared__ float h2[60];

    const float* posn = pos + n * 120;   // [5][4][6]

    if (tid < 120) {
        const int f = tid / 24;
        const int j = (tid / 6) % 4;
        const int d = tid % 6;
        float acc = frameb[d];
#pragma unroll
        for (int e = 0; e < 6; e++)
            acc = fmaf(posn[(f * 4 + j) * 6 + e], framew[d * 6 + e], acc);
        msg[tid] = acc;
        // nodes_feature slot of feat
        feat[f * 48 + j * 12 + d] = g_nf[(n * 20 + f * 4 + j) * 6 + d];
    }
    __syncthreads();

    if (tid < 120) {
        const int f  = tid / 24;
        const int nn = (tid / 6) % 4;
        const int d  = tid % 6;
        const float* att = attmap + n * 80 + f * 16;
        float acc = 0.f;
#pragma unroll
        for (int j = 0; j < 4; j++)
            acc = fmaf(att[j * 4 + nn], msg[f * 24 + j * 6 + d], acc);
        if (f >= 1) {
            float l = lastb[d];
#pragma unroll
            for (int e = 0; e < 6; e++)
                l = fmaf(posn[((f - 1) * 4 + nn) * 6 + e], lastw[d * 6 + e], l);
            acc += l;
        }
        feat[f * 48 + nn * 12 + 6 + d] = acc;
    }
    __syncthreads();

    if (tid < 120) {
        float acc = fc1b[tid];
        const float* wr = fc1w + tid * 240;
#pragma unroll 8
        for (int k = 0; k < 240; k++) acc = fmaf(feat[k], wr[k], acc);
        h1[tid] = fmaxf(acc, 0.f);
    }
    __syncthreads();

    if (tid < 60) {
        float acc = fc2b[tid];
        const float* wr = fc2w + tid * 120;
#pragma unroll 8
        for (int k = 0; k < 120; k++) acc = fmaf(h1[k], wr[k], acc);
        h2[tid] = fmaxf(acc, 0.f);
    }
    __syncthreads();

    if (tid < 6) {
        float acc = fc3b[tid];
#pragma unroll
        for (int k = 0; k < 60; k++) acc = fmaf(h2[k], fc3w[tid * 60 + k], acc);
        out[n * 6 + tid] = acc;
    }
}

// ---------------------------------------------------------------------------
extern "C" void kernel_launch(void* const* d_in, const int* in_sizes, int n_in,
                              void* d_out, int out_size)
{
    const float* nodes  = (const float*)d_in[0];
    const float* pos    = (const float*)d_in[1];
    const float* attmap = (const float*)d_in[2];
    // d_in[3] = depths (unused)
    const float* conv1w = (const float*)d_in[4];
    const float* conv1b = (const float*)d_in[5];
    const float* conv2w = (const float*)d_in[6];
    const float* conv2b = (const float*)d_in[7];
    const float* linw   = (const float*)d_in[8];
    const float* linb   = (const float*)d_in[9];
    const float* framew = (const float*)d_in[10];
    const float* frameb = (const float*)d_in[11];
    const float* lastw  = (const float*)d_in[12];
    const float* lastb  = (const float*)d_in[13];
    const float* fc1w   = (const float*)d_in[14];
    const float* fc1b   = (const float*)d_in[15];
    const float* fc2w   = (const float*)d_in[16];
    const float* fc2b   = (const float*)d_in[17];
    const float* fc3w   = (const float*)d_in[18];
    const float* fc3b   = (const float*)d_in[19];

    dim3 g1(IMGS, 19);
    stage1_kernel<<<g1, 128>>>(nodes, conv1w, conv1b);
    stage2_kernel<<<IMGS, 128>>>(conv2w, conv2b, linw, linb);
    stage3_kernel<<<64, 128>>>(pos, attmap, framew, frameb, lastw, lastb,
                               fc1w, fc1b, fc2w, fc2b, fc3w, fc3b,
                               (float*)d_out);
}